// round 10
// baseline (speedup 1.0000x reference)
#include <cuda_runtime.h>

#define NN 50000
#define EPC 64             // edges per CTA
#define FTH 256            // 8 warps: 4 h-warps (w0..3) + 4 g-warps (w4..7)

__device__ float g_P[(size_t)8 * NN * 64];
__device__ float g_agg[(size_t)NN * 64];

__device__ __forceinline__ float sigm_(float x) { return __fdividef(1.f, 1.f + __expf(-x)); }
__device__ __forceinline__ float silu_(float x) { return x * sigm_(x); }
__device__ __forceinline__ float tf32r(float x) {
    float y; asm("cvt.rna.tf32.f32 %0, %1;" : "=f"(y) : "f"(x)); return y;
}

// m16n8k8 tf32 HMMA, D += A*B (C==D)
__device__ __forceinline__ void mma8(float* d, const unsigned* a, const unsigned* b) {
    asm volatile("mma.sync.aligned.m16n8k8.row.col.f32.tf32.tf32.f32 "
        "{%0,%1,%2,%3},{%4,%5,%6,%7},{%8,%9},{%0,%1,%2,%3};"
        : "+f"(d[0]), "+f"(d[1]), "+f"(d[2]), "+f"(d[3])
        : "r"(a[0]), "r"(a[1]), "r"(a[2]), "r"(a[3]), "r"(b[0]), "r"(b[1]));
}

// ==================== projection kernel ====================
__global__ __launch_bounds__(256) void proj_mma_kernel(
    const float* __restrict__ nf, const float* __restrict__ eW1,
    const float* __restrict__ egW1, const float* __restrict__ nW1,
    const float* __restrict__ ngW1)
{
    extern __shared__ float sm[];
    float* sB = sm;           // 64 x 136
    float* sA = sm + 8704;    // 128 x 68

    int tid = threadIdx.x;
    int g = blockIdx.y;
    const float* W = (g == 0) ? eW1 : (g == 1) ? egW1 : (g == 2) ? nW1 : ngW1;
    int m0 = blockIdx.x * 128;

    for (int i = tid; i < 64 * 128; i += 256) {
        int k = i >> 7, n = i & 127;
        float v = (n < 64) ? W[k * 64 + n] : W[(128 + k) * 64 + (n - 64)];
        sB[k * 136 + n] = tf32r(v);
    }
    for (int i = tid; i < 128 * 64; i += 256) {
        int m = i >> 6, k = i & 63;
        int node = m0 + m;
        sA[m * 68 + k] = tf32r(node < NN ? nf[(size_t)node * 64 + k] : 0.f);
    }
    __syncthreads();

    int lane = tid & 31, w = tid >> 5, gid = lane >> 2, tig = lane & 3;
    int r0 = 16 * w + gid, r1 = r0 + 8;

    float acc[16][4];
    #pragma unroll
    for (int nt = 0; nt < 16; nt++)
        acc[nt][0] = acc[nt][1] = acc[nt][2] = acc[nt][3] = 0.f;

    #pragma unroll 2
    for (int kt = 0; kt < 8; kt++) {
        int k0 = kt * 8;
        unsigned a[4];
        a[0] = __float_as_uint(sA[r0 * 68 + k0 + tig]);
        a[1] = __float_as_uint(sA[r1 * 68 + k0 + tig]);
        a[2] = __float_as_uint(sA[r0 * 68 + k0 + tig + 4]);
        a[3] = __float_as_uint(sA[r1 * 68 + k0 + tig + 4]);
        const float* bp0 = sB + (k0 + tig) * 136 + gid;
        const float* bp1 = bp0 + 4 * 136;
        #pragma unroll
        for (int nt = 0; nt < 16; nt++) {
            unsigned b[2] = { __float_as_uint(bp0[8 * nt]), __float_as_uint(bp1[8 * nt]) };
            mma8(acc[nt], a, b);
        }
    }

    int n0g = m0 + r0, n1g = m0 + r1;
    #pragma unroll
    for (int nt = 0; nt < 16; nt++) {
        int slot = 2 * g + (nt >> 3);
        int c = ((nt & 7) << 3) + 2 * tig;
        float* base = g_P + (size_t)slot * NN * 64;
        if (n0g < NN) *(float2*)(base + (size_t)n0g * 64 + c) = make_float2(acc[nt][0], acc[nt][1]);
        if (n1g < NN) *(float2*)(base + (size_t)n1g * 64 + c) = make_float2(acc[nt][2], acc[nt][3]);
    }
}

__global__ void zero_agg_kernel() {
    size_t i = (size_t)blockIdx.x * 256 + threadIdx.x;
    if (i < (size_t)NN * 64) g_agg[i] = 0.f;
}

// ==================== fused edge+node kernel ====================
// 64 edges/CTA, 8 warps. Pair (w, w+4): warp w computes h, warp w+4 computes g
// for rows 16*(w&3).. ; epilogue split by column halves -> fully balanced.
// Single B buffer time-multiplexed: eW1 -> eW2 -> nW1 -> nW2.
__global__ void __launch_bounds__(FTH, 3) fused_kernel(
    const float* __restrict__ ef, const int* __restrict__ src,
    const int* __restrict__ dst, const float* __restrict__ rbf,
    const float* __restrict__ sew, const float* __restrict__ snw,
    const float* __restrict__ eW1, const float* __restrict__ eb1,
    const float* __restrict__ eW2, const float* __restrict__ eb2,
    const float* __restrict__ egW1, const float* __restrict__ egb1,
    const float* __restrict__ egW2, const float* __restrict__ egb2,
    const float* __restrict__ nW1, const float* __restrict__ nb1,
    const float* __restrict__ nW2, const float* __restrict__ nb2,
    const float* __restrict__ ngW1, const float* __restrict__ ngb1,
    const float* __restrict__ ngW2, const float* __restrict__ ngb2,
    const float* __restrict__ ewf, const float* __restrict__ nwf,
    float* __restrict__ outEdge, int E)
{
    extern __shared__ float sm[];
    float* sB   = sm;             // 8704: current W [k][n<64: h | n>=64: g]
    float* sSH  = sm + 8704;      // 64x68 = 4352: ef / h-hidden / new_ef
    float* sSG  = sm + 13056;     // 4352: g-hidden / activation exchange
    float* sWF  = sm + 17408;     // 576: ewf then nwf
    float* sRBF = sm + 17984;     // 640 (64 x 10)
    float* sBias = sm + 18624;    // 512: eb1|egb1|eb2|egb2|nb1|ngb1|nb2|ngb2
    // total 19136 floats = 76544 B  -> 3 CTAs/SM

    int tid = threadIdx.x, lane = tid & 31, w = tid >> 5;
    bool isG = w >= 4;
    int pr = w & 3;
    int gid = lane >> 2, tig = lane & 3;
    int r0 = 16 * pr + gid, r1 = r0 + 8;
    int e0 = blockIdx.x * EPC;
    size_t eg0 = (size_t)e0 + r0, eg1 = (size_t)e0 + r1;
    bool v0 = eg0 < (size_t)E, v1 = eg1 < (size_t)E;
    int s0 = v0 ? src[eg0] : 0, d0 = v0 ? dst[eg0] : 0;
    int s1 = v1 ? src[eg1] : 0, d1 = v1 ? dst[eg1] : 0;

    // ---- initial cooperative loads ----
    for (int i = tid; i < 8192; i += FTH) {
        int k = i >> 7, n = i & 127;
        sB[k * 136 + n] = tf32r(n < 64 ? eW1[(64 + k) * 64 + n] : egW1[(64 + k) * 64 + (n - 64)]);
    }
    for (int i = tid; i < EPC * 64; i += FTH) {
        int m = i >> 6, k = i & 63;
        int e = e0 + m;
        sSH[m * 68 + k] = tf32r(e < E ? ef[(size_t)e * 64 + k] : 0.f);
    }
    for (int i = tid; i < 576; i += FTH) sWF[i] = ewf[i];
    for (int i = tid; i < EPC * 9; i += FTH) {
        int m = i / 9, r = i - 9 * m;
        int e = e0 + m;
        sRBF[m * 10 + r] = (e < E) ? rbf[(size_t)e * 9 + r] : 0.f;
    }
    if (tid < 64) {
        sBias[tid]       = eb1[tid]; sBias[64 + tid]  = egb1[tid];
        sBias[128 + tid] = eb2[tid]; sBias[192 + tid] = egb2[tid];
        sBias[256 + tid] = nb1[tid]; sBias[320 + tid] = ngb1[tid];
        sBias[384 + tid] = nb2[tid]; sBias[448 + tid] = ngb2[tid];
    }
    __syncthreads();   // S0

    int cOff = isG ? 64 : 0;
    float* stMine = isG ? sSG : sSH;
    float acc[8][4];
    float hv[8][2];    // post-activation values (h-warp: silu(h2+b2); g-warp: sigm(g2+gb2))

    // ================= EDGE HALF =================
    {
        const float* Ai = g_P + (size_t)(isG ? 2 : 0) * NN * 64;
        const float* Aj = g_P + (size_t)(isG ? 3 : 1) * NN * 64;
        const float* bb = sBias + (isG ? 64 : 0);
        #pragma unroll
        for (int nt = 0; nt < 8; nt++) {
            int c = 8 * nt + 2 * tig;
            float2 i0 = *(const float2*)(Ai + (size_t)s0 * 64 + c);
            float2 j0 = *(const float2*)(Aj + (size_t)d0 * 64 + c);
            float2 i1 = *(const float2*)(Ai + (size_t)s1 * 64 + c);
            float2 j1 = *(const float2*)(Aj + (size_t)d1 * 64 + c);
            float bx = bb[c], by = bb[c + 1];
            acc[nt][0] = i0.x + j0.x + bx; acc[nt][1] = i0.y + j0.y + by;
            acc[nt][2] = i1.x + j1.x + bx; acc[nt][3] = i1.y + j1.y + by;
        }
        // phase1: A = ef (sSH)
        #pragma unroll
        for (int kt = 0; kt < 8; kt++) {
            int k0 = 8 * kt;
            unsigned a[4];
            a[0] = __float_as_uint(sSH[r0 * 68 + k0 + tig]);
            a[1] = __float_as_uint(sSH[r1 * 68 + k0 + tig]);
            a[2] = __float_as_uint(sSH[r0 * 68 + k0 + tig + 4]);
            a[3] = __float_as_uint(sSH[r1 * 68 + k0 + tig + 4]);
            const float* bp0 = sB + (k0 + tig) * 136 + cOff + gid;
            const float* bp1 = bp0 + 4 * 136;
            #pragma unroll
            for (int nt = 0; nt < 8; nt++) {
                unsigned b[2] = { __float_as_uint(bp0[8 * nt]), __float_as_uint(bp1[8 * nt]) };
                mma8(acc[nt], a, b);
            }
        }
        __syncthreads();   // S1: phase1 reads of sSH/sB done

        // stage silu(hidden1); reload sB <- eW2|egW2
        #pragma unroll
        for (int nt = 0; nt < 8; nt++) {
            int c = 8 * nt + 2 * tig;
            *(float2*)(stMine + r0 * 68 + c) = make_float2(tf32r(silu_(acc[nt][0])), tf32r(silu_(acc[nt][1])));
            *(float2*)(stMine + r1 * 68 + c) = make_float2(tf32r(silu_(acc[nt][2])), tf32r(silu_(acc[nt][3])));
            acc[nt][0] = acc[nt][1] = acc[nt][2] = acc[nt][3] = 0.f;
        }
        for (int i = tid; i < 8192; i += FTH) {
            int k = i >> 7, n = i & 127;
            sB[k * 136 + n] = tf32r(n < 64 ? eW2[k * 64 + n] : egW2[k * 64 + (n - 64)]);
        }
        __syncthreads();   // S2

        // phase2: A = own hidden (sSH for h / sSG for g)
        #pragma unroll
        for (int kt = 0; kt < 8; kt++) {
            int k0 = 8 * kt;
            unsigned a[4];
            a[0] = __float_as_uint(stMine[r0 * 68 + k0 + tig]);
            a[1] = __float_as_uint(stMine[r1 * 68 + k0 + tig]);
            a[2] = __float_as_uint(stMine[r0 * 68 + k0 + tig + 4]);
            a[3] = __float_as_uint(stMine[r1 * 68 + k0 + tig + 4]);
            const float* bp0 = sB + (k0 + tig) * 136 + cOff + gid;
            const float* bp1 = bp0 + 4 * 136;
            #pragma unroll
            for (int nt = 0; nt < 8; nt++) {
                unsigned b[2] = { __float_as_uint(bp0[8 * nt]), __float_as_uint(bp1[8 * nt]) };
                mma8(acc[nt], a, b);
            }
        }
        __syncthreads();   // S3: phase2 reads of sSG/sSH done

        // activation + exchange: h publishes cols 32..63, g publishes cols 0..31
        const float* b2p = sBias + (isG ? 192 : 128);
        #pragma unroll
        for (int nt = 0; nt < 8; nt++) {
            int c = 8 * nt + 2 * tig;
            float bx = b2p[c], by = b2p[c + 1];
            if (isG) {
                hv[nt][0] = sigm_(acc[nt][0] + bx); hv[nt][1] = sigm_(acc[nt][1] + by);
                float s2 = sigm_(acc[nt][2] + bx), s3 = sigm_(acc[nt][3] + by);
                if (nt < 4) {
                    *(float2*)(sSG + r0 * 68 + c) = make_float2(hv[nt][0], hv[nt][1]);
                    *(float2*)(sSG + r1 * 68 + c) = make_float2(s2, s3);
                }
                hv[nt][0] = s2;  // keep row1 values for nt>=4 in hv? store both rows:
                // repack: for g-warp we need rows r0,r1 of nt>=4 later; keep in acc
                acc[nt][0] = sigm_(acc[nt][0] + bx); acc[nt][1] = sigm_(acc[nt][1] + by);
                acc[nt][2] = s2; acc[nt][3] = s3;
            } else {
                acc[nt][0] = silu_(acc[nt][0] + bx); acc[nt][1] = silu_(acc[nt][1] + by);
                acc[nt][2] = silu_(acc[nt][2] + bx); acc[nt][3] = silu_(acc[nt][3] + by);
                if (nt >= 4) {
                    *(float2*)(sSG + r0 * 68 + c) = make_float2(acc[nt][0], acc[nt][1]);
                    *(float2*)(sSG + r1 * 68 + c) = make_float2(acc[nt][2], acc[nt][3]);
                }
            }
        }
        __syncthreads();   // S4

        // epilogue: h-warp -> cols 0..31 (nt 0..3); g-warp -> cols 32..63 (nt 4..7)
        int ntA = isG ? 4 : 0;
        #pragma unroll
        for (int q = 0; q < 4; q++) {
            int nt = ntA + q;
            int c = 8 * nt + 2 * tig;
            float2 other0 = *(const float2*)(sSG + r0 * 68 + c);
            float2 other1 = *(const float2*)(sSG + r1 * 68 + c);
            float p00, p01, p10, p11;
            if (isG) {  // other = silu(h2), own acc = sigm(g2)
                p00 = other0.x * acc[nt][0]; p01 = other0.y * acc[nt][1];
                p10 = other1.x * acc[nt][2]; p11 = other1.y * acc[nt][3];
            } else {    // own acc = silu(h2), other = sigm(g2)
                p00 = acc[nt][0] * other0.x; p01 = acc[nt][1] * other0.y;
                p10 = acc[nt][2] * other1.x; p11 = acc[nt][3] * other1.y;
            }
            float wf00 = 0.f, wf01 = 0.f, wf10 = 0.f, wf11 = 0.f;
            #pragma unroll
            for (int r = 0; r < 9; r++) {
                float2 wv = *(const float2*)(sWF + r * 64 + c);
                float rv0 = sRBF[r0 * 10 + r], rv1 = sRBF[r1 * 10 + r];
                wf00 += rv0 * wv.x; wf01 += rv0 * wv.y;
                wf10 += rv1 * wv.x; wf11 += rv1 * wv.y;
            }
            float n00 = 0.f, n01 = 0.f, n10 = 0.f, n11 = 0.f;
            if (v0) {
                float2 swv = *(const float2*)(sew + eg0 * 64 + c);
                float2 ev  = *(const float2*)(ef + eg0 * 64 + c);
                n00 = ev.x + p00 * wf00 * swv.x;
                n01 = ev.y + p01 * wf01 * swv.y;
                *(float2*)(outEdge + eg0 * 64 + c) = make_float2(n00, n01);
            }
            if (v1) {
                float2 swv = *(const float2*)(sew + eg1 * 64 + c);
                float2 ev  = *(const float2*)(ef + eg1 * 64 + c);
                n10 = ev.x + p10 * wf10 * swv.x;
                n11 = ev.y + p11 * wf11 * swv.y;
                *(float2*)(outEdge + eg1 * 64 + c) = make_float2(n10, n11);
            }
            *(float2*)(sSH + r0 * 68 + c) = make_float2(tf32r(n00), tf32r(n01));
            *(float2*)(sSH + r1 * 68 + c) = make_float2(tf32r(n10), tf32r(n11));
        }
        // concurrently reload sB <- nW1|ngW1 (phase2 reads done at S3)
        for (int i = tid; i < 8192; i += FTH) {
            int k = i >> 7, n = i & 127;
            sB[k * 136 + n] = tf32r(n < 64 ? nW1[(64 + k) * 64 + n] : ngW1[(64 + k) * 64 + (n - 64)]);
        }
    }
    __syncthreads();   // S5

    // ================= NODE HALF =================
    {
        const float* Ai = g_P + (size_t)(isG ? 6 : 4) * NN * 64;
        const float* Aj = g_P + (size_t)(isG ? 7 : 5) * NN * 64;
        const float* bb = sBias + 256 + (isG ? 64 : 0);
        #pragma unroll
        for (int nt = 0; nt < 8; nt++) {
            int c = 8 * nt + 2 * tig;
            float2 i0 = *(const float2*)(Ai + (size_t)s0 * 64 + c);
            float2 j0 = *(const float2*)(Aj + (size_t)d0 * 64 + c);
            float2 i1 = *(const float2*)(Ai + (size_t)s1 * 64 + c);
            float2 j1 = *(const float2*)(Aj + (size_t)d1 * 64 + c);
            float bx = bb[c], by = bb[c + 1];
            acc[nt][0] = i0.x + j0.x + bx; acc[nt][1] = i0.y + j0.y + by;
            acc[nt][2] = i1.x + j1.x + bx; acc[nt][3] = i1.y + j1.y + by;
        }
        // phase1: A = new_ef (sSH)
        #pragma unroll
        for (int kt = 0; kt < 8; kt++) {
            int k0 = 8 * kt;
            unsigned a[4];
            a[0] = __float_as_uint(sSH[r0 * 68 + k0 + tig]);
            a[1] = __float_as_uint(sSH[r1 * 68 + k0 + tig]);
            a[2] = __float_as_uint(sSH[r0 * 68 + k0 + tig + 4]);
            a[3] = __float_as_uint(sSH[r1 * 68 + k0 + tig + 4]);
            const float* bp0 = sB + (k0 + tig) * 136 + cOff + gid;
            const float* bp1 = bp0 + 4 * 136;
            #pragma unroll
            for (int nt = 0; nt < 8; nt++) {
                unsigned b[2] = { __float_as_uint(bp0[8 * nt]), __float_as_uint(bp1[8 * nt]) };
                mma8(acc[nt], a, b);
            }
        }
        __syncthreads();   // S6

        // stage silu(hidden1); reload sB <- nW2|ngW2 ; sWF <- nwf
        #pragma unroll
        for (int nt = 0; nt < 8; nt++) {
            int c = 8 * nt + 2 * tig;
            *(float2*)(stMine + r0 * 68 + c) = make_float2(tf32r(silu_(acc[nt][0])), tf32r(silu_(acc[nt][1])));
            *(float2*)(stMine + r1 * 68 + c) = make_float2(tf32r(silu_(acc[nt][2])), tf32r(silu_(acc[nt][3])));
            acc[nt][0] = acc[nt][1] = acc[nt][2] = acc[nt][3] = 0.f;
        }
        for (int i = tid; i < 8192; i += FTH) {
            int k = i >> 7, n = i & 127;
            sB[k * 136 + n] = tf32r(n < 64 ? nW2[k * 64 + n] : ngW2[k * 64 + (n - 64)]);
        }
        for (int i = tid; i < 576; i += FTH) sWF[i] = nwf[i];
        __syncthreads();   // S7

        // phase2
        #pragma unroll
        for (int kt = 0; kt < 8; kt++) {
            int k0 = 8 * kt;
            unsigned a[4];
            a[0] = __float_as_uint(stMine[r0 * 68 + k0 + tig]);
            a[1] = __float_as_uint(stMine[r1 * 68 + k0 + tig]);
            a[2] = __float_as_uint(stMine[r0 * 68 + k0 + tig + 4]);
            a[3] = __float_as_uint(stMine[r1 * 68 + k0 + tig + 4]);
            const float* bp0 = sB + (k0 + tig) * 136 + cOff + gid;
            const float* bp1 = bp0 + 4 * 136;
            #pragma unroll
            for (int nt = 0; nt < 8; nt++) {
                unsigned b[2] = { __float_as_uint(bp0[8 * nt]), __float_as_uint(bp1[8 * nt]) };
                mma8(acc[nt], a, b);
            }
        }
        __syncthreads();   // S8

        // activation + exchange
        const float* b2p = sBias + 384 + (isG ? 64 : 0);
        #pragma unroll
        for (int nt = 0; nt < 8; nt++) {
            int c = 8 * nt + 2 * tig;
            float bx = b2p[c], by = b2p[c + 1];
            if (isG) {
                acc[nt][0] = sigm_(acc[nt][0] + bx); acc[nt][1] = sigm_(acc[nt][1] + by);
                acc[nt][2] = sigm_(acc[nt][2] + bx); acc[nt][3] = sigm_(acc[nt][3] + by);
                if (nt < 4) {
                    *(float2*)(sSG + r0 * 68 + c) = make_float2(acc[nt][0], acc[nt][1]);
                    *(float2*)(sSG + r1 * 68 + c) = make_float2(acc[nt][2], acc[nt][3]);
                }
            } else {
                acc[nt][0] = silu_(acc[nt][0] + bx); acc[nt][1] = silu_(acc[nt][1] + by);
                acc[nt][2] = silu_(acc[nt][2] + bx); acc[nt][3] = silu_(acc[nt][3] + by);
                if (nt >= 4) {
                    *(float2*)(sSG + r0 * 68 + c) = make_float2(acc[nt][0], acc[nt][1]);
                    *(float2*)(sSG + r1 * 68 + c) = make_float2(acc[nt][2], acc[nt][3]);
                }
            }
        }
        __syncthreads();   // S9

        // epilogue with atomics, split by column halves
        int ntA = isG ? 4 : 0;
        #pragma unroll
        for (int q = 0; q < 4; q++) {
            int nt = ntA + q;
            int c = 8 * nt + 2 * tig;
            float2 other0 = *(const float2*)(sSG + r0 * 68 + c);
            float2 other1 = *(const float2*)(sSG + r1 * 68 + c);
            float p00 = acc[nt][0] * other0.x, p01 = acc[nt][1] * other0.y;
            float p10 = acc[nt][2] * other1.x, p11 = acc[nt][3] * other1.y;
            float wf00 = 0.f, wf01 = 0.f, wf10 = 0.f, wf11 = 0.f;
            #pragma unroll
            for (int r = 0; r < 9; r++) {
                float2 wv = *(const float2*)(sWF + r * 64 + c);
                float rv0 = sRBF[r0 * 10 + r], rv1 = sRBF[r1 * 10 + r];
                wf00 += rv0 * wv.x; wf01 += rv0 * wv.y;
                wf10 += rv1 * wv.x; wf11 += rv1 * wv.y;
            }
            if (v0) {
                float2 swv = *(const float2*)(snw + eg0 * 64 + c);
                atomicAdd(&g_agg[(size_t)d0 * 64 + c],     p00 * wf00 * swv.x);
                atomicAdd(&g_agg[(size_t)d0 * 64 + c + 1], p01 * wf01 * swv.y);
            }
            if (v1) {
                float2 swv = *(const float2*)(snw + eg1 * 64 + c);
                atomicAdd(&g_agg[(size_t)d1 * 64 + c],     p10 * wf10 * swv.x);
                atomicAdd(&g_agg[(size_t)d1 * 64 + c + 1], p11 * wf11 * swv.y);
            }
        }
    }
}

// ==================== node output ====================
__global__ __launch_bounds__(256) void nodeout_kernel(
    const float* __restrict__ nf, const float* __restrict__ Wout,
    float* __restrict__ out)
{
    __shared__ float sAG[4096];
    __shared__ float sW[4096];
    int tid = threadIdx.x;
    int m0 = blockIdx.x * 64;
    for (int i = tid; i < 1024; i += 256) {
        ((float4*)sW)[i] = ((const float4*)Wout)[i];
        int m = i >> 4;
        float4 v = make_float4(0.f, 0.f, 0.f, 0.f);
        if (m0 + m < NN) v = *(const float4*)&g_agg[(size_t)(m0 + m) * 64 + 4 * (i & 15)];
        ((float4*)sAG)[i] = v;
    }
    __syncthreads();
    int tx = tid & 15, ty = tid >> 4, n0 = 4 * tx;
    float acc[4][4] = {};
    #pragma unroll 16
    for (int k = 0; k < 64; k++) {
        float a0 = sAG[(4*ty+0)*64+k], a1 = sAG[(4*ty+1)*64+k];
        float a2 = sAG[(4*ty+2)*64+k], a3 = sAG[(4*ty+3)*64+k];
        float4 b = *(const float4*)&sW[k * 64 + n0];
        acc[0][0]+=a0*b.x; acc[0][1]+=a0*b.y; acc[0][2]+=a0*b.z; acc[0][3]+=a0*b.w;
        acc[1][0]+=a1*b.x; acc[1][1]+=a1*b.y; acc[1][2]+=a1*b.z; acc[1][3]+=a1*b.w;
        acc[2][0]+=a2*b.x; acc[2][1]+=a2*b.y; acc[2][2]+=a2*b.z; acc[2][3]+=a2*b.w;
        acc[3][0]+=a3*b.x; acc[3][1]+=a3*b.y; acc[3][2]+=a3*b.z; acc[3][3]+=a3*b.w;
    }
    #pragma unroll
    for (int i = 0; i < 4; i++) {
        int m = m0 + 4 * ty + i;
        if (m < NN) {
            float4 base = *(const float4*)&nf[(size_t)m * 64 + n0];
            *(float4*)&out[(size_t)m * 64 + n0] = make_float4(
                base.x + acc[i][0], base.y + acc[i][1], base.z + acc[i][2], base.w + acc[i][3]);
        }
    }
}

// ==================== launch ====================
extern "C" void kernel_launch(void* const* d_in, const int* in_sizes, int n_in,
                              void* d_out, int out_size) {
    const float* nf   = (const float*)d_in[0];
    const float* ef   = (const float*)d_in[1];
    const int*   src  = (const int*)d_in[2];
    const int*   dst  = (const int*)d_in[3];
    const float* rbf  = (const float*)d_in[4];
    const float* snw  = (const float*)d_in[5];
    const float* sew  = (const float*)d_in[6];
    const float* eW1  = (const float*)d_in[7];
    const float* eb1  = (const float*)d_in[8];
    const float* eW2  = (const float*)d_in[9];
    const float* eb2  = (const float*)d_in[10];
    const float* egW1 = (const float*)d_in[11];
    const float* egb1 = (const float*)d_in[12];
    const float* egW2 = (const float*)d_in[13];
    const float* egb2 = (const float*)d_in[14];
    const float* nW1  = (const float*)d_in[15];
    const float* nb1  = (const float*)d_in[16];
    const float* nW2  = (const float*)d_in[17];
    const float* nb2  = (const float*)d_in[18];
    const float* ngW1 = (const float*)d_in[19];
    const float* ngb1 = (const float*)d_in[20];
    const float* ngW2 = (const float*)d_in[21];
    const float* ngb2 = (const float*)d_in[22];
    const float* WoutM = (const float*)d_in[23];
    const float* nwf  = (const float*)d_in[24];
    const float* ewf  = (const float*)d_in[25];

    int E = in_sizes[2];
    float* outNode = (float*)d_out;
    float* outEdge = outNode + (size_t)NN * 64;

    const int FSM = 19136 * 4;   // 76544 B -> 3 CTAs/SM
    const int PSM = 17408 * 4;   // 69632 B
    static int configured = 0;
    if (!configured) {
        cudaFuncSetAttribute(fused_kernel, cudaFuncAttributeMaxDynamicSharedMemorySize, FSM);
        cudaFuncSetAttribute(proj_mma_kernel, cudaFuncAttributeMaxDynamicSharedMemorySize, PSM);
        configured = 1;
    }

    dim3 gP((NN + 127) / 128, 4);
    proj_mma_kernel<<<gP, 256, PSM>>>(nf, eW1, egW1, nW1, ngW1);

    zero_agg_kernel<<<((size_t)NN * 64 + 255) / 256, 256>>>();

    int gE = (E + EPC - 1) / EPC;
    fused_kernel<<<gE, FTH, FSM>>>(
        ef, src, dst, rbf, sew, snw,
        eW1, eb1, eW2, eb2, egW1, egb1, egW2, egb2,
        nW1, nb1, nW2, nb2, ngW1, ngb1, ngW2, ngb2,
        ewf, nwf, outEdge, E);

    nodeout_kernel<<<(NN + 63) / 64, 256>>>(nf, WoutM, outNode);
}

// round 11
// speedup vs baseline: 1.5564x; 1.5564x over previous
#include <cuda_runtime.h>

#define NN 50000
#define EPC 128
#define GRID_F 304   // ~2 CTAs/SM persistent

__device__ float g_P[(size_t)8 * NN * 64];
__device__ float g_agg[(size_t)NN * 64];

__device__ __forceinline__ float sigm_(float x) { return __fdividef(1.f, 1.f + __expf(-x)); }
__device__ __forceinline__ float silu_(float x) { return x * sigm_(x); }
__device__ __forceinline__ float tf32r(float x) {
    float y; asm("cvt.rna.tf32.f32 %0, %1;" : "=f"(y) : "f"(x)); return y;
}

// m16n8k8 tf32 HMMA, D += A*B (C==D)
__device__ __forceinline__ void mma8(float* d, const unsigned* a, const unsigned* b) {
    asm volatile("mma.sync.aligned.m16n8k8.row.col.f32.tf32.tf32.f32 "
        "{%0,%1,%2,%3},{%4,%5,%6,%7},{%8,%9},{%0,%1,%2,%3};"
        : "+f"(d[0]), "+f"(d[1]), "+f"(d[2]), "+f"(d[3])
        : "r"(a[0]), "r"(a[1]), "r"(a[2]), "r"(a[3]), "r"(b[0]), "r"(b[1]));
}

// ==================== projection kernel ====================
__global__ __launch_bounds__(256) void proj_mma_kernel(
    const float* __restrict__ nf, const float* __restrict__ eW1,
    const float* __restrict__ egW1, const float* __restrict__ nW1,
    const float* __restrict__ ngW1)
{
    extern __shared__ float sm[];
    float* sB = sm;           // 64 x 136
    float* sA = sm + 8704;    // 128 x 68

    int tid = threadIdx.x;
    int g = blockIdx.y;
    const float* W = (g == 0) ? eW1 : (g == 1) ? egW1 : (g == 2) ? nW1 : ngW1;
    int m0 = blockIdx.x * 128;

    for (int i = tid; i < 64 * 128; i += 256) {
        int k = i >> 7, n = i & 127;
        float v = (n < 64) ? W[k * 64 + n] : W[(128 + k) * 64 + (n - 64)];
        sB[k * 136 + n] = tf32r(v);
    }
    for (int i = tid; i < 128 * 64; i += 256) {
        int m = i >> 6, k = i & 63;
        int node = m0 + m;
        sA[m * 68 + k] = tf32r(node < NN ? nf[(size_t)node * 64 + k] : 0.f);
    }
    __syncthreads();

    int lane = tid & 31, w = tid >> 5, gid = lane >> 2, tig = lane & 3;
    int r0 = 16 * w + gid, r1 = r0 + 8;

    float acc[16][4];
    #pragma unroll
    for (int nt = 0; nt < 16; nt++)
        acc[nt][0] = acc[nt][1] = acc[nt][2] = acc[nt][3] = 0.f;

    #pragma unroll 2
    for (int kt = 0; kt < 8; kt++) {
        int k0 = kt * 8;
        unsigned a[4];
        a[0] = __float_as_uint(sA[r0 * 68 + k0 + tig]);
        a[1] = __float_as_uint(sA[r1 * 68 + k0 + tig]);
        a[2] = __float_as_uint(sA[r0 * 68 + k0 + tig + 4]);
        a[3] = __float_as_uint(sA[r1 * 68 + k0 + tig + 4]);
        const float* bp0 = sB + (k0 + tig) * 136 + gid;
        const float* bp1 = bp0 + 4 * 136;
        #pragma unroll
        for (int nt = 0; nt < 16; nt++) {
            unsigned b[2] = { __float_as_uint(bp0[8 * nt]), __float_as_uint(bp1[8 * nt]) };
            mma8(acc[nt], a, b);
        }
    }

    int n0g = m0 + r0, n1g = m0 + r1;
    #pragma unroll
    for (int nt = 0; nt < 16; nt++) {
        int slot = 2 * g + (nt >> 3);
        int c = ((nt & 7) << 3) + 2 * tig;
        float* base = g_P + (size_t)slot * NN * 64;
        if (n0g < NN) *(float2*)(base + (size_t)n0g * 64 + c) = make_float2(acc[nt][0], acc[nt][1]);
        if (n1g < NN) *(float2*)(base + (size_t)n1g * 64 + c) = make_float2(acc[nt][2], acc[nt][3]);
    }
}

__global__ void zero_agg_kernel() {
    size_t i = (size_t)blockIdx.x * 256 + threadIdx.x;
    if (i < (size_t)NN * 64) g_agg[i] = 0.f;
}

// ==================== fused persistent edge+node kernel ====================
// 256 threads (8 warps); grid-stride over 128-edge tiles. Warp owns 16 rows.
// All row state is warp-private -> NO __syncthreads inside the tile loops.
__global__ void __launch_bounds__(256, 2) fused_kernel(
    const float* __restrict__ ef, const int* __restrict__ src,
    const int* __restrict__ dst, const float* __restrict__ rbf,
    const float* __restrict__ sew, const float* __restrict__ snw,
    const float* __restrict__ eW1, const float* __restrict__ eb1,
    const float* __restrict__ eW2, const float* __restrict__ eb2,
    const float* __restrict__ egW1, const float* __restrict__ egb1,
    const float* __restrict__ egW2, const float* __restrict__ egb2,
    const float* __restrict__ nW1, const float* __restrict__ nb1,
    const float* __restrict__ nW2, const float* __restrict__ nb2,
    const float* __restrict__ ngW1, const float* __restrict__ ngb1,
    const float* __restrict__ ngW2, const float* __restrict__ ngb2,
    const float* __restrict__ ewf, const float* __restrict__ nwf,
    float* __restrict__ outEdge, int E, int nTiles)
{
    extern __shared__ float sm[];
    float* sB1   = sm;            // 8704: phase1 W [k][n<64: h | n>=64: g]
    float* sB2   = sm + 8704;     // 8704: phase2 W
    float* sSt   = sm + 17408;    // 128x68 = 8704: warp-private stage
    float* sWF   = sm + 26112;    // 576
    float* sBias = sm + 26688;    // 256: b1 | gb1 | b2 | gb2
    // total 26944 floats = 107776 B -> 2 CTAs/SM

    int tid = threadIdx.x, lane = tid & 31, w = tid >> 5;
    int gid = lane >> 2, tig = lane & 3;
    int r0 = 16 * w + gid, r1 = r0 + 8;
    float acc[16][4];

    // ---- load edge-phase weights once ----
    for (int i = tid; i < 8192; i += 256) {
        int k = i >> 7, n = i & 127;
        sB1[k * 136 + n] = tf32r(n < 64 ? eW1[(64 + k) * 64 + n] : egW1[(64 + k) * 64 + (n - 64)]);
        sB2[k * 136 + n] = tf32r(n < 64 ? eW2[k * 64 + n] : egW2[k * 64 + (n - 64)]);
    }
    for (int i = tid; i < 576; i += 256) sWF[i] = ewf[i];
    if (tid < 64) {
        sBias[tid] = eb1[tid]; sBias[64 + tid] = egb1[tid];
        sBias[128 + tid] = eb2[tid]; sBias[192 + tid] = egb2[tid];
    }
    __syncthreads();

    // ================= EDGE PASS =================
    for (int t = blockIdx.x; t < nTiles; t += gridDim.x) {
        int e0 = t * EPC;
        size_t eg0 = (size_t)e0 + r0, eg1 = (size_t)e0 + r1;
        bool v0 = eg0 < (size_t)E, v1 = eg1 < (size_t)E;
        int s0 = v0 ? src[eg0] : 0, d0 = v0 ? dst[eg0] : 0;
        int s1 = v1 ? src[eg1] : 0, d1 = v1 ? dst[eg1] : 0;

        // stage ef rows (warp-private): lane covers cols 16*tig..16*tig+15 of rows r0,r1
        #pragma unroll
        for (int rr = 0; rr < 2; rr++) {
            int row = rr ? r1 : r0;
            size_t eg = rr ? eg1 : eg0;
            bool v = rr ? v1 : v0;
            #pragma unroll
            for (int q = 0; q < 4; q++) {
                float4 x = make_float4(0.f, 0.f, 0.f, 0.f);
                if (v) x = *(const float4*)(ef + eg * 64 + 16 * tig + 4 * q);
                float* dp = sSt + row * 68 + 16 * tig + 4 * q;
                dp[0] = tf32r(x.x); dp[1] = tf32r(x.y); dp[2] = tf32r(x.z); dp[3] = tf32r(x.w);
            }
        }

        // C-init = Pi[s]+Pj[d]+b1 (h: slots 0,1 ; g: slots 2,3)
        #pragma unroll
        for (int nt = 0; nt < 16; nt++) {
            int c = ((nt & 7) << 3) + 2 * tig;
            const float* Ai = g_P + (size_t)(nt < 8 ? 0 : 2) * NN * 64;
            const float* Aj = g_P + (size_t)(nt < 8 ? 1 : 3) * NN * 64;
            const float* bb = (nt < 8) ? sBias : (sBias + 64);
            float2 i0 = *(const float2*)(Ai + (size_t)s0 * 64 + c);
            float2 j0 = *(const float2*)(Aj + (size_t)d0 * 64 + c);
            float2 i1 = *(const float2*)(Ai + (size_t)s1 * 64 + c);
            float2 j1 = *(const float2*)(Aj + (size_t)d1 * 64 + c);
            float bx = bb[c], by = bb[c + 1];
            acc[nt][0] = i0.x + j0.x + bx; acc[nt][1] = i0.y + j0.y + by;
            acc[nt][2] = i1.x + j1.x + bx; acc[nt][3] = i1.y + j1.y + by;
        }
        __syncwarp();

        // phase1: A = ef rows
        #pragma unroll 2
        for (int kt = 0; kt < 8; kt++) {
            int k0 = 8 * kt;
            unsigned a[4];
            a[0] = __float_as_uint(sSt[r0 * 68 + k0 + tig]);
            a[1] = __float_as_uint(sSt[r1 * 68 + k0 + tig]);
            a[2] = __float_as_uint(sSt[r0 * 68 + k0 + tig + 4]);
            a[3] = __float_as_uint(sSt[r1 * 68 + k0 + tig + 4]);
            const float* bp0 = sB1 + (k0 + tig) * 136 + gid;
            const float* bp1 = bp0 + 4 * 136;
            #pragma unroll
            for (int nt = 0; nt < 16; nt++) {
                unsigned b[2] = { __float_as_uint(bp0[8 * nt]), __float_as_uint(bp1[8 * nt]) };
                mma8(acc[nt], a, b);
            }
        }
        __syncwarp();

        // stage silu(h1) over own rows; zero acc h
        #pragma unroll
        for (int nt = 0; nt < 8; nt++) {
            int c = 8 * nt + 2 * tig;
            *(float2*)(sSt + r0 * 68 + c) = make_float2(tf32r(silu_(acc[nt][0])), tf32r(silu_(acc[nt][1])));
            *(float2*)(sSt + r1 * 68 + c) = make_float2(tf32r(silu_(acc[nt][2])), tf32r(silu_(acc[nt][3])));
            acc[nt][0] = acc[nt][1] = acc[nt][2] = acc[nt][3] = 0.f;
        }
        __syncwarp();
        // phase2-h
        #pragma unroll 2
        for (int kt = 0; kt < 8; kt++) {
            int k0 = 8 * kt;
            unsigned a[4];
            a[0] = __float_as_uint(sSt[r0 * 68 + k0 + tig]);
            a[1] = __float_as_uint(sSt[r1 * 68 + k0 + tig]);
            a[2] = __float_as_uint(sSt[r0 * 68 + k0 + tig + 4]);
            a[3] = __float_as_uint(sSt[r1 * 68 + k0 + tig + 4]);
            const float* bp0 = sB2 + (k0 + tig) * 136 + gid;
            const float* bp1 = bp0 + 4 * 136;
            #pragma unroll
            for (int nt = 0; nt < 8; nt++) {
                unsigned b[2] = { __float_as_uint(bp0[8 * nt]), __float_as_uint(bp1[8 * nt]) };
                mma8(acc[nt], a, b);
            }
        }
        __syncwarp();
        // stage silu(g1); zero acc g
        #pragma unroll
        for (int nt = 8; nt < 16; nt++) {
            int c = 8 * (nt - 8) + 2 * tig;
            *(float2*)(sSt + r0 * 68 + c) = make_float2(tf32r(silu_(acc[nt][0])), tf32r(silu_(acc[nt][1])));
            *(float2*)(sSt + r1 * 68 + c) = make_float2(tf32r(silu_(acc[nt][2])), tf32r(silu_(acc[nt][3])));
            acc[nt][0] = acc[nt][1] = acc[nt][2] = acc[nt][3] = 0.f;
        }
        __syncwarp();
        // phase2-g
        #pragma unroll 2
        for (int kt = 0; kt < 8; kt++) {
            int k0 = 8 * kt;
            unsigned a[4];
            a[0] = __float_as_uint(sSt[r0 * 68 + k0 + tig]);
            a[1] = __float_as_uint(sSt[r1 * 68 + k0 + tig]);
            a[2] = __float_as_uint(sSt[r0 * 68 + k0 + tig + 4]);
            a[3] = __float_as_uint(sSt[r1 * 68 + k0 + tig + 4]);
            const float* bp0 = sB2 + (k0 + tig) * 136 + 64 + gid;
            const float* bp1 = bp0 + 4 * 136;
            #pragma unroll
            for (int nt = 8; nt < 16; nt++) {
                unsigned b[2] = { __float_as_uint(bp0[8 * (nt - 8)]), __float_as_uint(bp1[8 * (nt - 8)]) };
                mma8(acc[nt], a, b);
            }
        }

        // epilogue (own rows): new_ef -> global
        float rb0[9], rb1[9];
        #pragma unroll
        for (int r = 0; r < 9; r++) {
            rb0[r] = v0 ? rbf[eg0 * 9 + r] : 0.f;
            rb1[r] = v1 ? rbf[eg1 * 9 + r] : 0.f;
        }
        #pragma unroll
        for (int nt = 0; nt < 8; nt++) {
            int c = 8 * nt + 2 * tig;
            float b2x = sBias[128 + c], b2y = sBias[128 + c + 1];
            float gbx = sBias[192 + c], gby = sBias[192 + c + 1];
            float h00 = silu_(acc[nt][0] + b2x), h01 = silu_(acc[nt][1] + b2y);
            float h10 = silu_(acc[nt][2] + b2x), h11 = silu_(acc[nt][3] + b2y);
            float g00 = sigm_(acc[nt + 8][0] + gbx), g01 = sigm_(acc[nt + 8][1] + gby);
            float g10 = sigm_(acc[nt + 8][2] + gbx), g11 = sigm_(acc[nt + 8][3] + gby);
            float wf00 = 0.f, wf01 = 0.f, wf10 = 0.f, wf11 = 0.f;
            #pragma unroll
            for (int r = 0; r < 9; r++) {
                float2 wv = *(const float2*)(sWF + r * 64 + c);
                wf00 += rb0[r] * wv.x; wf01 += rb0[r] * wv.y;
                wf10 += rb1[r] * wv.x; wf11 += rb1[r] * wv.y;
            }
            if (v0) {
                float2 swv = *(const float2*)(sew + eg0 * 64 + c);
                float2 ev  = *(const float2*)(ef + eg0 * 64 + c);
                *(float2*)(outEdge + eg0 * 64 + c) = make_float2(
                    ev.x + h00 * g00 * wf00 * swv.x, ev.y + h01 * g01 * wf01 * swv.y);
            }
            if (v1) {
                float2 swv = *(const float2*)(sew + eg1 * 64 + c);
                float2 ev  = *(const float2*)(ef + eg1 * 64 + c);
                *(float2*)(outEdge + eg1 * 64 + c) = make_float2(
                    ev.x + h10 * g10 * wf10 * swv.x, ev.y + h11 * g11 * wf11 * swv.y);
            }
        }
        __syncwarp();
    }

    // ---- swap to node-phase weights ----
    __syncthreads();
    for (int i = tid; i < 8192; i += 256) {
        int k = i >> 7, n = i & 127;
        sB1[k * 136 + n] = tf32r(n < 64 ? nW1[(64 + k) * 64 + n] : ngW1[(64 + k) * 64 + (n - 64)]);
        sB2[k * 136 + n] = tf32r(n < 64 ? nW2[k * 64 + n] : ngW2[k * 64 + (n - 64)]);
    }
    for (int i = tid; i < 576; i += 256) sWF[i] = nwf[i];
    if (tid < 64) {
        sBias[tid] = nb1[tid]; sBias[64 + tid] = ngb1[tid];
        sBias[128 + tid] = nb2[tid]; sBias[192 + tid] = ngb2[tid];
    }
    __syncthreads();

    // ================= NODE PASS =================
    for (int t = blockIdx.x; t < nTiles; t += gridDim.x) {
        int e0 = t * EPC;
        size_t eg0 = (size_t)e0 + r0, eg1 = (size_t)e0 + r1;
        bool v0 = eg0 < (size_t)E, v1 = eg1 < (size_t)E;
        int s0 = v0 ? src[eg0] : 0, d0 = v0 ? dst[eg0] : 0;
        int s1 = v1 ? src[eg1] : 0, d1 = v1 ? dst[eg1] : 0;

        // stage new_ef rows from outEdge (written by this CTA in edge pass)
        #pragma unroll
        for (int rr = 0; rr < 2; rr++) {
            int row = rr ? r1 : r0;
            size_t eg = rr ? eg1 : eg0;
            bool v = rr ? v1 : v0;
            #pragma unroll
            for (int q = 0; q < 4; q++) {
                float4 x = make_float4(0.f, 0.f, 0.f, 0.f);
                if (v) x = *(const float4*)(outEdge + eg * 64 + 16 * tig + 4 * q);
                float* dp = sSt + row * 68 + 16 * tig + 4 * q;
                dp[0] = tf32r(x.x); dp[1] = tf32r(x.y); dp[2] = tf32r(x.z); dp[3] = tf32r(x.w);
            }
        }

        #pragma unroll
        for (int nt = 0; nt < 16; nt++) {
            int c = ((nt & 7) << 3) + 2 * tig;
            const float* Ai = g_P + (size_t)(nt < 8 ? 4 : 6) * NN * 64;
            const float* Aj = g_P + (size_t)(nt < 8 ? 5 : 7) * NN * 64;
            const float* bb = (nt < 8) ? sBias : (sBias + 64);
            float2 i0 = *(const float2*)(Ai + (size_t)s0 * 64 + c);
            float2 j0 = *(const float2*)(Aj + (size_t)d0 * 64 + c);
            float2 i1 = *(const float2*)(Ai + (size_t)s1 * 64 + c);
            float2 j1 = *(const float2*)(Aj + (size_t)d1 * 64 + c);
            float bx = bb[c], by = bb[c + 1];
            acc[nt][0] = i0.x + j0.x + bx; acc[nt][1] = i0.y + j0.y + by;
            acc[nt][2] = i1.x + j1.x + bx; acc[nt][3] = i1.y + j1.y + by;
        }
        __syncwarp();

        #pragma unroll 2
        for (int kt = 0; kt < 8; kt++) {
            int k0 = 8 * kt;
            unsigned a[4];
            a[0] = __float_as_uint(sSt[r0 * 68 + k0 + tig]);
            a[1] = __float_as_uint(sSt[r1 * 68 + k0 + tig]);
            a[2] = __float_as_uint(sSt[r0 * 68 + k0 + tig + 4]);
            a[3] = __float_as_uint(sSt[r1 * 68 + k0 + tig + 4]);
            const float* bp0 = sB1 + (k0 + tig) * 136 + gid;
            const float* bp1 = bp0 + 4 * 136;
            #pragma unroll
            for (int nt = 0; nt < 16; nt++) {
                unsigned b[2] = { __float_as_uint(bp0[8 * nt]), __float_as_uint(bp1[8 * nt]) };
                mma8(acc[nt], a, b);
            }
        }
        __syncwarp();

        #pragma unroll
        for (int nt = 0; nt < 8; nt++) {
            int c = 8 * nt + 2 * tig;
            *(float2*)(sSt + r0 * 68 + c) = make_float2(tf32r(silu_(acc[nt][0])), tf32r(silu_(acc[nt][1])));
            *(float2*)(sSt + r1 * 68 + c) = make_float2(tf32r(silu_(acc[nt][2])), tf32r(silu_(acc[nt][3])));
            acc[nt][0] = acc[nt][1] = acc[nt][2] = acc[nt][3] = 0.f;
        }
        __syncwarp();
        #pragma unroll 2
        for (int kt = 0; kt < 8; kt++) {
            int k0 = 8 * kt;
            unsigned a[4];
            a[0] = __float_as_uint(sSt[r0 * 68 + k0 + tig]);
            a[1] = __float_as_uint(sSt[r1 * 68 + k0 + tig]);
            a[2] = __float_as_uint(sSt[r0 * 68 + k0 + tig + 4]);
            a[3] = __float_as_uint(sSt[r1 * 68 + k0 + tig + 4]);
            const float* bp0 = sB2 + (k0 + tig) * 136 + gid;
            const float* bp1 = bp0 + 4 * 136;
            #pragma unroll
            for (int nt = 0; nt < 8; nt++) {
                unsigned b[2] = { __float_as_uint(bp0[8 * nt]), __float_as_uint(bp1[8 * nt]) };
                mma8(acc[nt], a, b);
            }
        }
        __syncwarp();
        #pragma unroll
        for (int nt = 8; nt < 16; nt++) {
            int c = 8 * (nt - 8) + 2 * tig;
            *(float2*)(sSt + r0 * 68 + c) = make_float2(tf32r(silu_(acc[nt][0])), tf32r(silu_(acc[nt][1])));
            *(float2*)(sSt + r1 * 68 + c) = make_float2(tf32r(silu_(acc[nt][2])), tf32r(silu_(acc[nt][3])));
            acc[nt][0] = acc[nt][1] = acc[nt][2] = acc[nt][3] = 0.f;
        }
        __syncwarp();
        #pragma unroll 2
        for (int kt = 0; kt < 8; kt++) {
            int k0 = 8 * kt;
            unsigned a[4];
            a[0] = __float_as_uint(sSt[r0 * 68 + k0 + tig]);
            a[1] = __float_as_uint(sSt[r1 * 68 + k0 + tig]);
            a[2] = __float_as_uint(sSt[r0 * 68 + k0 + tig + 4]);
            a[3] = __float_as_uint(sSt[r1 * 68 + k0 + tig + 4]);
            const float* bp0 = sB2 + (k0 + tig) * 136 + 64 + gid;
            const float* bp1 = bp0 + 4 * 136;
            #pragma unroll
            for (int nt = 8; nt < 16; nt++) {
                unsigned b[2] = { __float_as_uint(bp0[8 * (nt - 8)]), __float_as_uint(bp1[8 * (nt - 8)]) };
                mma8(acc[nt], a, b);
            }
        }

        float rb0[9], rb1[9];
        #pragma unroll
        for (int r = 0; r < 9; r++) {
            rb0[r] = v0 ? rbf[eg0 * 9 + r] : 0.f;
            rb1[r] = v1 ? rbf[eg1 * 9 + r] : 0.f;
        }
        #pragma unroll
        for (int nt = 0; nt < 8; nt++) {
            int c = 8 * nt + 2 * tig;
            float b2x = sBias[128 + c], b2y = sBias[128 + c + 1];
            float gbx = sBias[192 + c], gby = sBias[192 + c + 1];
            float h00 = silu_(acc[nt][0] + b2x), h01 = silu_(acc[nt][1] + b2y);
            float h10 = silu_(acc[nt][2] + b2x), h11 = silu_(acc[nt][3] + b2y);
            float g00 = sigm_(acc[nt + 8][0] + gbx), g01 = sigm_(acc[nt + 8][1] + gby);
            float g10 = sigm_(acc[nt + 8][2] + gbx), g11 = sigm_(acc[nt + 8][3] + gby);
            float wf00 = 0.f, wf01 = 0.f, wf10 = 0.f, wf11 = 0.f;
            #pragma unroll
            for (int r = 0; r < 9; r++) {
                float2 wv = *(const float2*)(sWF + r * 64 + c);
                wf00 += rb0[r] * wv.x; wf01 += rb0[r] * wv.y;
                wf10 += rb1[r] * wv.x; wf11 += rb1[r] * wv.y;
            }
            if (v0) {
                float2 swv = *(const float2*)(snw + eg0 * 64 + c);
                atomicAdd(&g_agg[(size_t)d0 * 64 + c],     h00 * g00 * wf00 * swv.x);
                atomicAdd(&g_agg[(size_t)d0 * 64 + c + 1], h01 * g01 * wf01 * swv.y);
            }
            if (v1) {
                float2 swv = *(const float2*)(snw + eg1 * 64 + c);
                atomicAdd(&g_agg[(size_t)d1 * 64 + c],     h10 * g10 * wf10 * swv.x);
                atomicAdd(&g_agg[(size_t)d1 * 64 + c + 1], h11 * g11 * wf11 * swv.y);
            }
        }
        __syncwarp();
    }
}

// ==================== node output ====================
__global__ __launch_bounds__(256) void nodeout_kernel(
    const float* __restrict__ nf, const float* __restrict__ Wout,
    float* __restrict__ out)
{
    __shared__ float sAG[4096];
    __shared__ float sW[4096];
    int tid = threadIdx.x;
    int m0 = blockIdx.x * 64;
    for (int i = tid; i < 1024; i += 256) {
        ((float4*)sW)[i] = ((const float4*)Wout)[i];
        int m = i >> 4;
        float4 v = make_float4(0.f, 0.f, 0.f, 0.f);
        if (m0 + m < NN) v = *(const float4*)&g_agg[(size_t)(m0 + m) * 64 + 4 * (i & 15)];
        ((float4*)sAG)[i] = v;
    }
    __syncthreads();
    int tx = tid & 15, ty = tid >> 4, n0 = 4 * tx;
    float acc[4][4] = {};
    #pragma unroll 16
    for (int k = 0; k < 64; k++) {
        float a0 = sAG[(4*ty+0)*64+k], a1 = sAG[(4*ty+1)*64+k];
        float a2 = sAG[(4*ty+2)*64+k], a3 = sAG[(4*ty+3)*64+k];
        float4 b = *(const float4*)&sW[k * 64 + n0];
        acc[0][0]+=a0*b.x; acc[0][1]+=a0*b.y; acc[0][2]+=a0*b.z; acc[0][3]+=a0*b.w;
        acc[1][0]+=a1*b.x; acc[1][1]+=a1*b.y; acc[1][2]+=a1*b.z; acc[1][3]+=a1*b.w;
        acc[2][0]+=a2*b.x; acc[2][1]+=a2*b.y; acc[2][2]+=a2*b.z; acc[2][3]+=a2*b.w;
        acc[3][0]+=a3*b.x; acc[3][1]+=a3*b.y; acc[3][2]+=a3*b.z; acc[3][3]+=a3*b.w;
    }
    #pragma unroll
    for (int i = 0; i < 4; i++) {
        int m = m0 + 4 * ty + i;
        if (m < NN) {
            float4 base = *(const float4*)&nf[(size_t)m * 64 + n0];
            *(float4*)&out[(size_t)m * 64 + n0] = make_float4(
                base.x + acc[i][0], base.y + acc[i][1], base.z + acc[i][2], base.w + acc[i][3]);
        }
    }
}

// ==================== launch ====================
extern "C" void kernel_launch(void* const* d_in, const int* in_sizes, int n_in,
                              void* d_out, int out_size) {
    const float* nf   = (const float*)d_in[0];
    const float* ef   = (const float*)d_in[1];
    const int*   src  = (const int*)d_in[2];
    const int*   dst  = (const int*)d_in[3];
    const float* rbf  = (const float*)d_in[4];
    const float* snw  = (const float*)d_in[5];
    const float* sew  = (const float*)d_in[6];
    const float* eW1  = (const float*)d_in[7];
    const float* eb1  = (const float*)d_in[8];
    const float* eW2  = (const float*)d_in[9];
    const float* eb2  = (const float*)d_in[10];
    const float* egW1 = (const float*)d_in[11];
    const float* egb1 = (const float*)d_in[12];
    const float* egW2 = (const float*)d_in[13];
    const float* egb2 = (const float*)d_in[14];
    const float* nW1  = (const float*)d_in[15];
    const float* nb1  = (const float*)d_in[16];
    const float* nW2  = (const float*)d_in[17];
    const float* nb2  = (const float*)d_in[18];
    const float* ngW1 = (const float*)d_in[19];
    const float* ngb1 = (const float*)d_in[20];
    const float* ngW2 = (const float*)d_in[21];
    const float* ngb2 = (const float*)d_in[22];
    const float* WoutM = (const float*)d_in[23];
    const float* nwf  = (const float*)d_in[24];
    const float* ewf  = (const float*)d_in[25];

    int E = in_sizes[2];
    float* outNode = (float*)d_out;
    float* outEdge = outNode + (size_t)NN * 64;

    const int FSM = 26944 * 4;   // 107776 B -> 2 CTAs/SM
    const int PSM = 17408 * 4;   // 69632 B
    static int configured = 0;
    if (!configured) {
        cudaFuncSetAttribute(fused_kernel, cudaFuncAttributeMaxDynamicSharedMemorySize, FSM);
        cudaFuncSetAttribute(proj_mma_kernel, cudaFuncAttributeMaxDynamicSharedMemorySize, PSM);
        configured = 1;
    }

    dim3 gP((NN + 127) / 128, 4);
    proj_mma_kernel<<<gP, 256, PSM>>>(nf, eW1, egW1, nW1, ngW1);

    zero_agg_kernel<<<((size_t)NN * 64 + 255) / 256, 256>>>();

    int nTiles = (E + EPC - 1) / EPC;
    int grid = nTiles < GRID_F ? nTiles : GRID_F;
    fused_kernel<<<grid, 256, FSM>>>(
        ef, src, dst, rbf, sew, snw,
        eW1, eb1, eW2, eb2, egW1, egb1, egW2, egb2,
        nW1, nb1, nW2, nb2, ngW1, ngb1, ngW2, ngb2,
        ewf, nwf, outEdge, E, nTiles);

    nodeout_kernel<<<(NN + 63) / 64, 256>>>(nf, WoutM, outNode);
}

// round 12
// speedup vs baseline: 1.6285x; 1.0463x over previous
#include <cuda_runtime.h>

#define NN 50000
#define EPC 128
#define GRID_F 296   // exactly 2 CTAs/SM on 148 SMs

__device__ float g_P[(size_t)8 * NN * 64];
__device__ float g_agg[(size_t)NN * 64];

__device__ __forceinline__ float sigm_(float x) { return __fdividef(1.f, 1.f + __expf(-x)); }
__device__ __forceinline__ float silu_(float x) { return x * sigm_(x); }
__device__ __forceinline__ float tf32r(float x) {
    float y; asm("cvt.rna.tf32.f32 %0, %1;" : "=f"(y) : "f"(x)); return y;
}
__device__ __forceinline__ void pf2(const void* p) {
    asm volatile("prefetch.global.L2 [%0];" :: "l"(p));
}

// m16n8k8 tf32 HMMA, D += A*B (C==D)
__device__ __forceinline__ void mma8(float* d, const unsigned* a, const unsigned* b) {
    asm volatile("mma.sync.aligned.m16n8k8.row.col.f32.tf32.tf32.f32 "
        "{%0,%1,%2,%3},{%4,%5,%6,%7},{%8,%9},{%0,%1,%2,%3};"
        : "+f"(d[0]), "+f"(d[1]), "+f"(d[2]), "+f"(d[3])
        : "r"(a[0]), "r"(a[1]), "r"(a[2]), "r"(a[3]), "r"(b[0]), "r"(b[1]));
}

// ==================== projection kernel ====================
__global__ __launch_bounds__(256) void proj_mma_kernel(
    const float* __restrict__ nf, const float* __restrict__ eW1,
    const float* __restrict__ egW1, const float* __restrict__ nW1,
    const float* __restrict__ ngW1)
{
    extern __shared__ float sm[];
    float* sB = sm;           // 64 x 136
    float* sA = sm + 8704;    // 128 x 68

    int tid = threadIdx.x;
    int g = blockIdx.y;
    const float* W = (g == 0) ? eW1 : (g == 1) ? egW1 : (g == 2) ? nW1 : ngW1;
    int m0 = blockIdx.x * 128;

    for (int i = tid; i < 64 * 128; i += 256) {
        int k = i >> 7, n = i & 127;
        float v = (n < 64) ? W[k * 64 + n] : W[(128 + k) * 64 + (n - 64)];
        sB[k * 136 + n] = tf32r(v);
    }
    for (int i = tid; i < 128 * 64; i += 256) {
        int m = i >> 6, k = i & 63;
        int node = m0 + m;
        sA[m * 68 + k] = tf32r(node < NN ? nf[(size_t)node * 64 + k] : 0.f);
    }
    __syncthreads();

    int lane = tid & 31, w = tid >> 5, gid = lane >> 2, tig = lane & 3;
    int r0 = 16 * w + gid, r1 = r0 + 8;

    float acc[16][4];
    #pragma unroll
    for (int nt = 0; nt < 16; nt++)
        acc[nt][0] = acc[nt][1] = acc[nt][2] = acc[nt][3] = 0.f;

    #pragma unroll 2
    for (int kt = 0; kt < 8; kt++) {
        int k0 = kt * 8;
        unsigned a[4];
        a[0] = __float_as_uint(sA[r0 * 68 + k0 + tig]);
        a[1] = __float_as_uint(sA[r1 * 68 + k0 + tig]);
        a[2] = __float_as_uint(sA[r0 * 68 + k0 + tig + 4]);
        a[3] = __float_as_uint(sA[r1 * 68 + k0 + tig + 4]);
        const float* bp0 = sB + (k0 + tig) * 136 + gid;
        const float* bp1 = bp0 + 4 * 136;
        #pragma unroll
        for (int nt = 0; nt < 16; nt++) {
            unsigned b[2] = { __float_as_uint(bp0[8 * nt]), __float_as_uint(bp1[8 * nt]) };
            mma8(acc[nt], a, b);
        }
    }

    int n0g = m0 + r0, n1g = m0 + r1;
    #pragma unroll
    for (int nt = 0; nt < 16; nt++) {
        int slot = 2 * g + (nt >> 3);
        int c = ((nt & 7) << 3) + 2 * tig;
        float* base = g_P + (size_t)slot * NN * 64;
        if (n0g < NN) *(float2*)(base + (size_t)n0g * 64 + c) = make_float2(acc[nt][0], acc[nt][1]);
        if (n1g < NN) *(float2*)(base + (size_t)n1g * 64 + c) = make_float2(acc[nt][2], acc[nt][3]);
    }
}

__global__ void zero_agg_kernel() {
    size_t i = (size_t)blockIdx.x * 256 + threadIdx.x;
    if (i < (size_t)NN * 64) g_agg[i] = 0.f;
}

// ==================== fused persistent edge+node kernel ====================
__global__ void __launch_bounds__(256, 2) fused_kernel(
    const float* __restrict__ ef, const int* __restrict__ src,
    const int* __restrict__ dst, const float* __restrict__ rbf,
    const float* __restrict__ sew, const float* __restrict__ snw,
    const float* __restrict__ eW1, const float* __restrict__ eb1,
    const float* __restrict__ eW2, const float* __restrict__ eb2,
    const float* __restrict__ egW1, const float* __restrict__ egb1,
    const float* __restrict__ egW2, const float* __restrict__ egb2,
    const float* __restrict__ nW1, const float* __restrict__ nb1,
    const float* __restrict__ nW2, const float* __restrict__ nb2,
    const float* __restrict__ ngW1, const float* __restrict__ ngb1,
    const float* __restrict__ ngW2, const float* __restrict__ ngb2,
    const float* __restrict__ ewf, const float* __restrict__ nwf,
    float* __restrict__ outEdge, int E, int nTiles)
{
    extern __shared__ float sm[];
    float* sB1   = sm;            // 8704
    float* sB2   = sm + 8704;     // 8704
    float* sSt   = sm + 17408;    // 8704: warp-private stage
    float* sWF   = sm + 26112;    // 576
    float* sBias = sm + 26688;    // 256
    // total 26944 floats = 107776 B -> 2 CTAs/SM

    int tid = threadIdx.x, lane = tid & 31, w = tid >> 5;
    int gid = lane >> 2, tig = lane & 3;
    int r0 = 16 * w + gid, r1 = r0 + 8;
    float acc[16][4];

    for (int i = tid; i < 8192; i += 256) {
        int k = i >> 7, n = i & 127;
        sB1[k * 136 + n] = tf32r(n < 64 ? eW1[(64 + k) * 64 + n] : egW1[(64 + k) * 64 + (n - 64)]);
        sB2[k * 136 + n] = tf32r(n < 64 ? eW2[k * 64 + n] : egW2[k * 64 + (n - 64)]);
    }
    for (int i = tid; i < 576; i += 256) sWF[i] = ewf[i];
    if (tid < 64) {
        sBias[tid] = eb1[tid]; sBias[64 + tid] = egb1[tid];
        sBias[128 + tid] = eb2[tid]; sBias[192 + tid] = egb2[tid];
    }
    __syncthreads();

    // ================= EDGE PASS =================
    {
        int t = blockIdx.x;
        int sn0 = 0, dn0 = 0, sn1 = 0, dn1 = 0;
        if (t < nTiles) {
            size_t en0 = (size_t)t * EPC + r0, en1 = (size_t)t * EPC + r1;
            if (en0 < (size_t)E) { sn0 = src[en0]; dn0 = dst[en0]; }
            if (en1 < (size_t)E) { sn1 = src[en1]; dn1 = dst[en1]; }
        }
        for (; t < nTiles; t += gridDim.x) {
            int s0 = sn0, d0 = dn0, s1 = sn1, d1 = dn1;
            int e0 = t * EPC;
            size_t eg0 = (size_t)e0 + r0, eg1 = (size_t)e0 + r1;
            bool v0 = eg0 < (size_t)E, v1 = eg1 < (size_t)E;
            int tn = t + gridDim.x;
            size_t en0 = 0, en1 = 0;
            if (tn < nTiles) {
                en0 = (size_t)tn * EPC + r0; en1 = (size_t)tn * EPC + r1;
                sn0 = dn0 = sn1 = dn1 = 0;
                if (en0 < (size_t)E) { sn0 = src[en0]; dn0 = dst[en0]; }
                if (en1 < (size_t)E) { sn1 = src[en1]; dn1 = dst[en1]; }
            }

            // stage ef rows (warp-private)
            #pragma unroll
            for (int rr = 0; rr < 2; rr++) {
                int row = rr ? r1 : r0;
                size_t eg = rr ? eg1 : eg0;
                bool v = rr ? v1 : v0;
                #pragma unroll
                for (int q = 0; q < 4; q++) {
                    float4 x = make_float4(0.f, 0.f, 0.f, 0.f);
                    if (v) x = *(const float4*)(ef + eg * 64 + 16 * tig + 4 * q);
                    float* dp = sSt + row * 68 + 16 * tig + 4 * q;
                    dp[0] = tf32r(x.x); dp[1] = tf32r(x.y); dp[2] = tf32r(x.z); dp[3] = tf32r(x.w);
                }
            }

            // C-init
            #pragma unroll
            for (int nt = 0; nt < 16; nt++) {
                int c = ((nt & 7) << 3) + 2 * tig;
                const float* Ai = g_P + (size_t)(nt < 8 ? 0 : 2) * NN * 64;
                const float* Aj = g_P + (size_t)(nt < 8 ? 1 : 3) * NN * 64;
                const float* bb = (nt < 8) ? sBias : (sBias + 64);
                float2 i0 = *(const float2*)(Ai + (size_t)s0 * 64 + c);
                float2 j0 = *(const float2*)(Aj + (size_t)d0 * 64 + c);
                float2 i1 = *(const float2*)(Ai + (size_t)s1 * 64 + c);
                float2 j1 = *(const float2*)(Aj + (size_t)d1 * 64 + c);
                float bx = bb[c], by = bb[c + 1];
                acc[nt][0] = i0.x + j0.x + bx; acc[nt][1] = i0.y + j0.y + by;
                acc[nt][2] = i1.x + j1.x + bx; acc[nt][3] = i1.y + j1.y + by;
            }
            __syncwarp();

            // phase1
            #pragma unroll 2
            for (int kt = 0; kt < 8; kt++) {
                int k0 = 8 * kt;
                unsigned a[4];
                a[0] = __float_as_uint(sSt[r0 * 68 + k0 + tig]);
                a[1] = __float_as_uint(sSt[r1 * 68 + k0 + tig]);
                a[2] = __float_as_uint(sSt[r0 * 68 + k0 + tig + 4]);
                a[3] = __float_as_uint(sSt[r1 * 68 + k0 + tig + 4]);
                const float* bp0 = sB1 + (k0 + tig) * 136 + gid;
                const float* bp1 = bp0 + 4 * 136;
                #pragma unroll
                for (int nt = 0; nt < 16; nt++) {
                    unsigned b[2] = { __float_as_uint(bp0[8 * nt]), __float_as_uint(bp1[8 * nt]) };
                    mma8(acc[nt], a, b);
                }
            }

            // prefetch next tile's gather rows + ef rows (lane 0 of each quad)
            if (tn < nTiles && tig == 0) {
                pf2(g_P + (size_t)0 * NN * 64 + (size_t)sn0 * 64 + 2 * gid);
                pf2(g_P + (size_t)1 * NN * 64 + (size_t)dn0 * 64 + 2 * gid);
                pf2(g_P + (size_t)2 * NN * 64 + (size_t)sn0 * 64 + 2 * gid);
                pf2(g_P + (size_t)3 * NN * 64 + (size_t)dn0 * 64 + 2 * gid);
                pf2(g_P + (size_t)0 * NN * 64 + (size_t)sn1 * 64 + 2 * gid);
                pf2(g_P + (size_t)1 * NN * 64 + (size_t)dn1 * 64 + 2 * gid);
                pf2(g_P + (size_t)2 * NN * 64 + (size_t)sn1 * 64 + 2 * gid);
                pf2(g_P + (size_t)3 * NN * 64 + (size_t)dn1 * 64 + 2 * gid);
                if (en0 < (size_t)E) pf2(ef + en0 * 64 + 2 * gid);
                if (en1 < (size_t)E) pf2(ef + en1 * 64 + 2 * gid);
            }
            __syncwarp();

            // stage silu(h1)
            #pragma unroll
            for (int nt = 0; nt < 8; nt++) {
                int c = 8 * nt + 2 * tig;
                *(float2*)(sSt + r0 * 68 + c) = make_float2(tf32r(silu_(acc[nt][0])), tf32r(silu_(acc[nt][1])));
                *(float2*)(sSt + r1 * 68 + c) = make_float2(tf32r(silu_(acc[nt][2])), tf32r(silu_(acc[nt][3])));
                acc[nt][0] = acc[nt][1] = acc[nt][2] = acc[nt][3] = 0.f;
            }
            __syncwarp();
            // phase2-h
            #pragma unroll 2
            for (int kt = 0; kt < 8; kt++) {
                int k0 = 8 * kt;
                unsigned a[4];
                a[0] = __float_as_uint(sSt[r0 * 68 + k0 + tig]);
                a[1] = __float_as_uint(sSt[r1 * 68 + k0 + tig]);
                a[2] = __float_as_uint(sSt[r0 * 68 + k0 + tig + 4]);
                a[3] = __float_as_uint(sSt[r1 * 68 + k0 + tig + 4]);
                const float* bp0 = sB2 + (k0 + tig) * 136 + gid;
                const float* bp1 = bp0 + 4 * 136;
                #pragma unroll
                for (int nt = 0; nt < 8; nt++) {
                    unsigned b[2] = { __float_as_uint(bp0[8 * nt]), __float_as_uint(bp1[8 * nt]) };
                    mma8(acc[nt], a, b);
                }
            }
            __syncwarp();
            // stage silu(g1)
            #pragma unroll
            for (int nt = 8; nt < 16; nt++) {
                int c = 8 * (nt - 8) + 2 * tig;
                *(float2*)(sSt + r0 * 68 + c) = make_float2(tf32r(silu_(acc[nt][0])), tf32r(silu_(acc[nt][1])));
                *(float2*)(sSt + r1 * 68 + c) = make_float2(tf32r(silu_(acc[nt][2])), tf32r(silu_(acc[nt][3])));
                acc[nt][0] = acc[nt][1] = acc[nt][2] = acc[nt][3] = 0.f;
            }
            __syncwarp();
            // phase2-g
            #pragma unroll 2
            for (int kt = 0; kt < 8; kt++) {
                int k0 = 8 * kt;
                unsigned a[4];
                a[0] = __float_as_uint(sSt[r0 * 68 + k0 + tig]);
                a[1] = __float_as_uint(sSt[r1 * 68 + k0 + tig]);
                a[2] = __float_as_uint(sSt[r0 * 68 + k0 + tig + 4]);
                a[3] = __float_as_uint(sSt[r1 * 68 + k0 + tig + 4]);
                const float* bp0 = sB2 + (k0 + tig) * 136 + 64 + gid;
                const float* bp1 = bp0 + 4 * 136;
                #pragma unroll
                for (int nt = 8; nt < 16; nt++) {
                    unsigned b[2] = { __float_as_uint(bp0[8 * (nt - 8)]), __float_as_uint(bp1[8 * (nt - 8)]) };
                    mma8(acc[nt], a, b);
                }
            }

            // epilogue
            float rb0[9], rb1[9];
            #pragma unroll
            for (int r = 0; r < 9; r++) {
                rb0[r] = v0 ? rbf[eg0 * 9 + r] : 0.f;
                rb1[r] = v1 ? rbf[eg1 * 9 + r] : 0.f;
            }
            #pragma unroll
            for (int nt = 0; nt < 8; nt++) {
                int c = 8 * nt + 2 * tig;
                float b2x = sBias[128 + c], b2y = sBias[128 + c + 1];
                float gbx = sBias[192 + c], gby = sBias[192 + c + 1];
                float h00 = silu_(acc[nt][0] + b2x), h01 = silu_(acc[nt][1] + b2y);
                float h10 = silu_(acc[nt][2] + b2x), h11 = silu_(acc[nt][3] + b2y);
                float g00 = sigm_(acc[nt + 8][0] + gbx), g01 = sigm_(acc[nt + 8][1] + gby);
                float g10 = sigm_(acc[nt + 8][2] + gbx), g11 = sigm_(acc[nt + 8][3] + gby);
                float wf00 = 0.f, wf01 = 0.f, wf10 = 0.f, wf11 = 0.f;
                #pragma unroll
                for (int r = 0; r < 9; r++) {
                    float2 wv = *(const float2*)(sWF + r * 64 + c);
                    wf00 += rb0[r] * wv.x; wf01 += rb0[r] * wv.y;
                    wf10 += rb1[r] * wv.x; wf11 += rb1[r] * wv.y;
                }
                if (v0) {
                    float2 swv = *(const float2*)(sew + eg0 * 64 + c);
                    float2 ev  = *(const float2*)(ef + eg0 * 64 + c);
                    *(float2*)(outEdge + eg0 * 64 + c) = make_float2(
                        ev.x + h00 * g00 * wf00 * swv.x, ev.y + h01 * g01 * wf01 * swv.y);
                }
                if (v1) {
                    float2 swv = *(const float2*)(sew + eg1 * 64 + c);
                    float2 ev  = *(const float2*)(ef + eg1 * 64 + c);
                    *(float2*)(outEdge + eg1 * 64 + c) = make_float2(
                        ev.x + h10 * g10 * wf10 * swv.x, ev.y + h11 * g11 * wf11 * swv.y);
                }
            }
            __syncwarp();
        }
    }

    // ---- swap to node-phase weights ----
    __syncthreads();
    for (int i = tid; i < 8192; i += 256) {
        int k = i >> 7, n = i & 127;
        sB1[k * 136 + n] = tf32r(n < 64 ? nW1[(64 + k) * 64 + n] : ngW1[(64 + k) * 64 + (n - 64)]);
        sB2[k * 136 + n] = tf32r(n < 64 ? nW2[k * 64 + n] : ngW2[k * 64 + (n - 64)]);
    }
    for (int i = tid; i < 576; i += 256) sWF[i] = nwf[i];
    if (tid < 64) {
        sBias[tid] = nb1[tid]; sBias[64 + tid] = ngb1[tid];
        sBias[128 + tid] = nb2[tid]; sBias[192 + tid] = ngb2[tid];
    }
    __syncthreads();

    // ================= NODE PASS =================
    {
        int t = blockIdx.x;
        int sn0 = 0, dn0 = 0, sn1 = 0, dn1 = 0;
        if (t < nTiles) {
            size_t en0 = (size_t)t * EPC + r0, en1 = (size_t)t * EPC + r1;
            if (en0 < (size_t)E) { sn0 = src[en0]; dn0 = dst[en0]; }
            if (en1 < (size_t)E) { sn1 = src[en1]; dn1 = dst[en1]; }
        }
        for (int t2 = t; t2 < nTiles; t2 += gridDim.x) {
            int s0 = sn0, d0 = dn0, s1 = sn1, d1 = dn1;
            int e0 = t2 * EPC;
            size_t eg0 = (size_t)e0 + r0, eg1 = (size_t)e0 + r1;
            bool v0 = eg0 < (size_t)E, v1 = eg1 < (size_t)E;
            int tn = t2 + gridDim.x;
            size_t en0 = 0, en1 = 0;
            if (tn < nTiles) {
                en0 = (size_t)tn * EPC + r0; en1 = (size_t)tn * EPC + r1;
                sn0 = dn0 = sn1 = dn1 = 0;
                if (en0 < (size_t)E) { sn0 = src[en0]; dn0 = dst[en0]; }
                if (en1 < (size_t)E) { sn1 = src[en1]; dn1 = dst[en1]; }
            }

            // stage new_ef rows from outEdge
            #pragma unroll
            for (int rr = 0; rr < 2; rr++) {
                int row = rr ? r1 : r0;
                size_t eg = rr ? eg1 : eg0;
                bool v = rr ? v1 : v0;
                #pragma unroll
                for (int q = 0; q < 4; q++) {
                    float4 x = make_float4(0.f, 0.f, 0.f, 0.f);
                    if (v) x = *(const float4*)(outEdge + eg * 64 + 16 * tig + 4 * q);
                    float* dp = sSt + row * 68 + 16 * tig + 4 * q;
                    dp[0] = tf32r(x.x); dp[1] = tf32r(x.y); dp[2] = tf32r(x.z); dp[3] = tf32r(x.w);
                }
            }

            #pragma unroll
            for (int nt = 0; nt < 16; nt++) {
                int c = ((nt & 7) << 3) + 2 * tig;
                const float* Ai = g_P + (size_t)(nt < 8 ? 4 : 6) * NN * 64;
                const float* Aj = g_P + (size_t)(nt < 8 ? 5 : 7) * NN * 64;
                const float* bb = (nt < 8) ? sBias : (sBias + 64);
                float2 i0 = *(const float2*)(Ai + (size_t)s0 * 64 + c);
                float2 j0 = *(const float2*)(Aj + (size_t)d0 * 64 + c);
                float2 i1 = *(const float2*)(Ai + (size_t)s1 * 64 + c);
                float2 j1 = *(const float2*)(Aj + (size_t)d1 * 64 + c);
                float bx = bb[c], by = bb[c + 1];
                acc[nt][0] = i0.x + j0.x + bx; acc[nt][1] = i0.y + j0.y + by;
                acc[nt][2] = i1.x + j1.x + bx; acc[nt][3] = i1.y + j1.y + by;
            }
            __syncwarp();

            #pragma unroll 2
            for (int kt = 0; kt < 8; kt++) {
                int k0 = 8 * kt;
                unsigned a[4];
                a[0] = __float_as_uint(sSt[r0 * 68 + k0 + tig]);
                a[1] = __float_as_uint(sSt[r1 * 68 + k0 + tig]);
                a[2] = __float_as_uint(sSt[r0 * 68 + k0 + tig + 4]);
                a[3] = __float_as_uint(sSt[r1 * 68 + k0 + tig + 4]);
                const float* bp0 = sB1 + (k0 + tig) * 136 + gid;
                const float* bp1 = bp0 + 4 * 136;
                #pragma unroll
                for (int nt = 0; nt < 16; nt++) {
                    unsigned b[2] = { __float_as_uint(bp0[8 * nt]), __float_as_uint(bp1[8 * nt]) };
                    mma8(acc[nt], a, b);
                }
            }

            if (tn < nTiles && tig == 0) {
                pf2(g_P + (size_t)4 * NN * 64 + (size_t)sn0 * 64 + 2 * gid);
                pf2(g_P + (size_t)5 * NN * 64 + (size_t)dn0 * 64 + 2 * gid);
                pf2(g_P + (size_t)6 * NN * 64 + (size_t)sn0 * 64 + 2 * gid);
                pf2(g_P + (size_t)7 * NN * 64 + (size_t)dn0 * 64 + 2 * gid);
                pf2(g_P + (size_t)4 * NN * 64 + (size_t)sn1 * 64 + 2 * gid);
                pf2(g_P + (size_t)5 * NN * 64 + (size_t)dn1 * 64 + 2 * gid);
                pf2(g_P + (size_t)6 * NN * 64 + (size_t)sn1 * 64 + 2 * gid);
                pf2(g_P + (size_t)7 * NN * 64 + (size_t)dn1 * 64 + 2 * gid);
                if (en0 < (size_t)E) pf2(outEdge + en0 * 64 + 2 * gid);
                if (en1 < (size_t)E) pf2(outEdge + en1 * 64 + 2 * gid);
            }
            __syncwarp();

            #pragma unroll
            for (int nt = 0; nt < 8; nt++) {
                int c = 8 * nt + 2 * tig;
                *(float2*)(sSt + r0 * 68 + c) = make_float2(tf32r(silu_(acc[nt][0])), tf32r(silu_(acc[nt][1])));
                *(float2*)(sSt + r1 * 68 + c) = make_float2(tf32r(silu_(acc[nt][2])), tf32r(silu_(acc[nt][3])));
                acc[nt][0] = acc[nt][1] = acc[nt][2] = acc[nt][3] = 0.f;
            }
            __syncwarp();
            #pragma unroll 2
            for (int kt = 0; kt < 8; kt++) {
                int k0 = 8 * kt;
                unsigned a[4];
                a[0] = __float_as_uint(sSt[r0 * 68 + k0 + tig]);
                a[1] = __float_as_uint(sSt[r1 * 68 + k0 + tig]);
                a[2] = __float_as_uint(sSt[r0 * 68 + k0 + tig + 4]);
                a[3] = __float_as_uint(sSt[r1 * 68 + k0 + tig + 4]);
                const float* bp0 = sB2 + (k0 + tig) * 136 + gid;
                const float* bp1 = bp0 + 4 * 136;
                #pragma unroll
                for (int nt = 0; nt < 8; nt++) {
                    unsigned b[2] = { __float_as_uint(bp0[8 * nt]), __float_as_uint(bp1[8 * nt]) };
                    mma8(acc[nt], a, b);
                }
            }
            __syncwarp();
            #pragma unroll
            for (int nt = 8; nt < 16; nt++) {
                int c = 8 * (nt - 8) + 2 * tig;
                *(float2*)(sSt + r0 * 68 + c) = make_float2(tf32r(silu_(acc[nt][0])), tf32r(silu_(acc[nt][1])));
                *(float2*)(sSt + r1 * 68 + c) = make_float2(tf32r(silu_(acc[nt][2])), tf32r(silu_(acc[nt][3])));
                acc[nt][0] = acc[nt][1] = acc[nt][2] = acc[nt][3] = 0.f;
            }
            __syncwarp();
            #pragma unroll 2
            for (int kt = 0; kt < 8; kt++) {
                int k0 = 8 * kt;
                unsigned a[4];
                a[0] = __float_as_uint(sSt[r0 * 68 + k0 + tig]);
                a[1] = __float_as_uint(sSt[r1 * 68 + k0 + tig]);
                a[2] = __float_as_uint(sSt[r0 * 68 + k0 + tig + 4]);
                a[3] = __float_as_uint(sSt[r1 * 68 + k0 + tig + 4]);
                const float* bp0 = sB2 + (k0 + tig) * 136 + 64 + gid;
                const float* bp1 = bp0 + 4 * 136;
                #pragma unroll
                for (int nt = 8; nt < 16; nt++) {
                    unsigned b[2] = { __float_as_uint(bp0[8 * (nt - 8)]), __float_as_uint(bp1[8 * (nt - 8)]) };
                    mma8(acc[nt], a, b);
                }
            }

            float rb0[9], rb1[9];
            #pragma unroll
            for (int r = 0; r < 9; r++) {
                rb0[r] = v0 ? rbf[eg0 * 9 + r] : 0.f;
                rb1[r] = v1 ? rbf[eg1 * 9 + r] : 0.f;
            }
            #pragma unroll
            for (int nt = 0; nt < 8; nt++) {
                int c = 8 * nt + 2 * tig;
                float b2x = sBias[128 + c], b2y = sBias[128 + c + 1];
                float gbx = sBias[192 + c], gby = sBias[192 + c + 1];
                float h00 = silu_(acc[nt][0] + b2x), h01 = silu_(acc[nt][1] + b2y);
                float h10 = silu_(acc[nt][2] + b2x), h11 = silu_(acc[nt][3] + b2y);
                float g00 = sigm_(acc[nt + 8][0] + gbx), g01 = sigm_(acc[nt + 8][1] + gby);
                float g10 = sigm_(acc[nt + 8][2] + gbx), g11 = sigm_(acc[nt + 8][3] + gby);
                float wf00 = 0.f, wf01 = 0.f, wf10 = 0.f, wf11 = 0.f;
                #pragma unroll
                for (int r = 0; r < 9; r++) {
                    float2 wv = *(const float2*)(sWF + r * 64 + c);
                    wf00 += rb0[r] * wv.x; wf01 += rb0[r] * wv.y;
                    wf10 += rb1[r] * wv.x; wf11 += rb1[r] * wv.y;
                }
                if (v0) {
                    float2 swv = *(const float2*)(snw + eg0 * 64 + c);
                    atomicAdd(&g_agg[(size_t)d0 * 64 + c],     h00 * g00 * wf00 * swv.x);
                    atomicAdd(&g_agg[(size_t)d0 * 64 + c + 1], h01 * g01 * wf01 * swv.y);
                }
                if (v1) {
                    float2 swv = *(const float2*)(snw + eg1 * 64 + c);
                    atomicAdd(&g_agg[(size_t)d1 * 64 + c],     h10 * g10 * wf10 * swv.x);
                    atomicAdd(&g_agg[(size_t)d1 * 64 + c + 1], h11 * g11 * wf11 * swv.y);
                }
            }
            __syncwarp();
        }
    }
}

// ==================== node output ====================
__global__ __launch_bounds__(256) void nodeout_kernel(
    const float* __restrict__ nf, const float* __restrict__ Wout,
    float* __restrict__ out)
{
    __shared__ float sAG[4096];
    __shared__ float sW[4096];
    int tid = threadIdx.x;
    int m0 = blockIdx.x * 64;
    for (int i = tid; i < 1024; i += 256) {
        ((float4*)sW)[i] = ((const float4*)Wout)[i];
        int m = i >> 4;
        float4 v = make_float4(0.f, 0.f, 0.f, 0.f);
        if (m0 + m < NN) v = *(const float4*)&g_agg[(size_t)(m0 + m) * 64 + 4 * (i & 15)];
        ((float4*)sAG)[i] = v;
    }
    __syncthreads();
    int tx = tid & 15, ty = tid >> 4, n0 = 4 * tx;
    float acc[4][4] = {};
    #pragma unroll 16
    for (int k = 0; k < 64; k++) {
        float a0 = sAG[(4*ty+0)*64+k], a1 = sAG[(4*ty+1)*64+k];
        float a2 = sAG[(4*ty+2)*64+k], a3 = sAG[(4*ty+3)*64+k];
        float4 b = *(const float4*)&sW[k * 64 + n0];
        acc[0][0]+=a0*b.x; acc[0][1]+=a0*b.y; acc[0][2]+=a0*b.z; acc[0][3]+=a0*b.w;
        acc[1][0]+=a1*b.x; acc[1][1]+=a1*b.y; acc[1][2]+=a1*b.z; acc[1][3]+=a1*b.w;
        acc[2][0]+=a2*b.x; acc[2][1]+=a2*b.y; acc[2][2]+=a2*b.z; acc[2][3]+=a2*b.w;
        acc[3][0]+=a3*b.x; acc[3][1]+=a3*b.y; acc[3][2]+=a3*b.z; acc[3][3]+=a3*b.w;
    }
    #pragma unroll
    for (int i = 0; i < 4; i++) {
        int m = m0 + 4 * ty + i;
        if (m < NN) {
            float4 base = *(const float4*)&nf[(size_t)m * 64 + n0];
            *(float4*)&out[(size_t)m * 64 + n0] = make_float4(
                base.x + acc[i][0], base.y + acc[i][1], base.z + acc[i][2], base.w + acc[i][3]);
        }
    }
}

// ==================== launch ====================
extern "C" void kernel_launch(void* const* d_in, const int* in_sizes, int n_in,
                              void* d_out, int out_size) {
    const float* nf   = (const float*)d_in[0];
    const float* ef   = (const float*)d_in[1];
    const int*   src  = (const int*)d_in[2];
    const int*   dst  = (const int*)d_in[3];
    const float* rbf  = (const float*)d_in[4];
    const float* snw  = (const float*)d_in[5];
    const float* sew  = (const float*)d_in[6];
    const float* eW1  = (const float*)d_in[7];
    const float* eb1  = (const float*)d_in[8];
    const float* eW2  = (const float*)d_in[9];
    const float* eb2  = (const float*)d_in[10];
    const float* egW1 = (const float*)d_in[11];
    const float* egb1 = (const float*)d_in[12];
    const float* egW2 = (const float*)d_in[13];
    const float* egb2 = (const float*)d_in[14];
    const float* nW1  = (const float*)d_in[15];
    const float* nb1  = (const float*)d_in[16];
    const float* nW2  = (const float*)d_in[17];
    const float* nb2  = (const float*)d_in[18];
    const float* ngW1 = (const float*)d_in[19];
    const float* ngb1 = (const float*)d_in[20];
    const float* ngW2 = (const float*)d_in[21];
    const float* ngb2 = (const float*)d_in[22];
    const float* WoutM = (const float*)d_in[23];
    const float* nwf  = (const float*)d_in[24];
    const float* ewf  = (const float*)d_in[25];

    int E = in_sizes[2];
    float* outNode = (float*)d_out;
    float* outEdge = outNode + (size_t)NN * 64;

    const int FSM = 26944 * 4;
    const int PSM = 17408 * 4;
    static int configured = 0;
    if (!configured) {
        cudaFuncSetAttribute(fused_kernel, cudaFuncAttributeMaxDynamicSharedMemorySize, FSM);
        cudaFuncSetAttribute(proj_mma_kernel, cudaFuncAttributeMaxDynamicSharedMemorySize, PSM);
        configured = 1;
    }

    dim3 gP((NN + 127) / 128, 4);
    proj_mma_kernel<<<gP, 256, PSM>>>(nf, eW1, egW1, nW1, ngW1);

    zero_agg_kernel<<<((size_t)NN * 64 + 255) / 256, 256>>>();

    int nTiles = (E + EPC - 1) / EPC;
    int grid = nTiles < GRID_F ? nTiles : GRID_F;
    fused_kernel<<<grid, 256, FSM>>>(
        ef, src, dst, rbf, sew, snw,
        eW1, eb1, eW2, eb2, egW1, egb1, egW2, egb2,
        nW1, nb1, nW2, nb2, ngW1, ngb1, ngW2, ngb2,
        ewf, nwf, outEdge, E, nTiles);

    nodeout_kernel<<<(NN + 63) / 64, 256>>>(nf, WoutM, outNode);
}